// round 8
// baseline (speedup 1.0000x reference)
#include <cuda_runtime.h>
#include <cuda_fp16.h>
#include <math.h>
#include <stdint.h>

#define T_TOK  8192
#define DMODEL 1024
#define HDIM   2048
#define NEXP   8
#define CAP    8192

#define KTILE  64                         // k-tile in halves (128 B rows)
#define ABUF   (128 * 128)                // 16384 B per 128 x 64-half tile
#define STAGE  (2 * ABUF)                 // A + B per stage
#define SMEM_BYTES (3 * STAGE)            // 98304 B, 3-stage pipeline
#define SC_LD  132                        // fp32 C staging stride

// prep kernel block regions
#define RB    1024                        // router blocks (8 warps each)
#define ZB    8192                        // out-zero blocks
#define CB    8192                        // cvt blocks per weight

// ---------------- device scratch (static, allocation-free) ----------------
__device__ int    g_cnt[NEXP];
__device__ int    g_tok[NEXP * CAP];
__device__ float  g_gate[NEXP * CAP];
__device__ __half g_xh[(size_t)T_TOK * DMODEL];
__device__ __half g_w1h[(size_t)NEXP * HDIM * DMODEL];
__device__ __half g_w3h[(size_t)NEXP * HDIM * DMODEL];
__device__ __half g_w2h[(size_t)NEXP * DMODEL * HDIM];
__device__ __half g_hh[(size_t)NEXP * CAP * HDIM];

// ---------------- PTX helpers (plain sm_80/sm_90-class) ----------------
__device__ __forceinline__ uint32_t smem_u32(const void* p) {
    uint32_t a;
    asm("{ .reg .u64 t; cvta.to.shared.u64 t, %1; cvt.u32.u64 %0, t; }" : "=r"(a) : "l"(p));
    return a;
}
#define CP_ASYNC16(dst, src) \
    asm volatile("cp.async.cg.shared.global [%0], [%1], 16;" :: "r"(dst), "l"(src))
#define CP_COMMIT() asm volatile("cp.async.commit_group;" ::: "memory")
#define CP_WAIT(n)  asm volatile("cp.async.wait_group %0;" :: "n"(n) : "memory")

__device__ __forceinline__ void ldsm_x4(uint32_t* r, uint32_t addr) {
    asm volatile("ldmatrix.sync.aligned.m8n8.x4.shared.b16 {%0,%1,%2,%3}, [%4];"
                 : "=r"(r[0]), "=r"(r[1]), "=r"(r[2]), "=r"(r[3]) : "r"(addr));
}
__device__ __forceinline__ void mma_f16(float* c, const uint32_t* a, const uint32_t* b) {
    asm volatile("mma.sync.aligned.m16n8k16.row.col.f32.f16.f16.f32 "
                 "{%0,%1,%2,%3}, {%4,%5,%6,%7}, {%8,%9}, {%0,%1,%2,%3};"
                 : "+f"(c[0]), "+f"(c[1]), "+f"(c[2]), "+f"(c[3])
                 : "r"(a[0]), "r"(a[1]), "r"(a[2]), "r"(a[3]), "r"(b[0]), "r"(b[1]));
}
__device__ __forceinline__ uint32_t pack2(float lo, float hi) {
    __half2 h = __floats2half2_rn(lo, hi);
    return *reinterpret_cast<uint32_t*>(&h);
}
__device__ __forceinline__ void red_add_v4(float* p, float a, float b, float c, float d) {
    asm volatile("red.global.add.v4.f32 [%0], {%1, %2, %3, %4};"
                 :: "l"(p), "f"(a), "f"(b), "f"(c), "f"(d) : "memory");
}

// swizzled smem byte offset for row r (128B rows), 16B segment s (0..7)
#define SWOFF(r, s16) ((uint32_t)((r) * 128 + (((s16) * 16) ^ (((r) & 7) << 4))))

// ---------------------------------------------------------------------------
// k_prep: fused router + out-zero + 3x weight fp32->fp16 convert.
// ---------------------------------------------------------------------------
__global__ void __launch_bounds__(256) k_prep(
    const float* __restrict__ x, const float* __restrict__ noise,
    const float* __restrict__ rw, const float* __restrict__ rb,
    const float* __restrict__ nw, const float* __restrict__ nb,
    const float4* __restrict__ w1, const float4* __restrict__ w3,
    const float4* __restrict__ w2, float4* __restrict__ out)
{
    const int b   = blockIdx.x;
    const int tid = threadIdx.x;

    if (b >= RB) {
        const int rb_ = b - RB;
        if (rb_ < ZB) {                                   // zero out (float4)
            out[(size_t)rb_ * 256 + tid] = make_float4(0.f, 0.f, 0.f, 0.f);
        } else {                                          // weight convert
            const int region = (rb_ - ZB) / CB;
            const size_t i = (size_t)((rb_ - ZB) % CB) * 256 + tid;
            const float4* s = (region == 0) ? w1 : (region == 1) ? w3 : w2;
            uint4* d = (uint4*)((region == 0) ? g_w1h : (region == 1) ? g_w3h : g_w2h);
            const float4 a0 = s[2 * i], b0 = s[2 * i + 1];
            uint4 o;
            o.x = pack2(a0.x, a0.y); o.y = pack2(a0.z, a0.w);
            o.z = pack2(b0.x, b0.y); o.w = pack2(b0.z, b0.w);
            d[i] = o;
        }
        return;
    }

    // ---- router: 8 warps, one token per warp ----
    const int warp = tid >> 5;
    const int lane = tid & 31;
    const int t = b * 8 + warp;

    const float4* xp  = (const float4*)(x + (size_t)t * DMODEL);
    const float4* rw4 = (const float4*)rw;
    const float4* nw4 = (const float4*)nw;
    uint2* xh = (uint2*)(g_xh + (size_t)t * DMODEL);

    float accR[NEXP], accN[NEXP];
#pragma unroll
    for (int j = 0; j < NEXP; j++) { accR[j] = 0.f; accN[j] = 0.f; }

#pragma unroll
    for (int it = 0; it < 8; it++) {
        const int d4 = it * 32 + lane;
        const float4 xv = xp[d4];
        uint2 p; p.x = pack2(xv.x, xv.y); p.y = pack2(xv.z, xv.w);
        xh[d4] = p;
#pragma unroll
        for (int j = 0; j < NEXP; j++) {
            const float4 w  = __ldg(rw4 + j * 256 + d4);
            accR[j] += xv.x * w.x + xv.y * w.y + xv.z * w.z + xv.w * w.w;
            const float4 wn = __ldg(nw4 + j * 256 + d4);
            accN[j] += xv.x * wn.x + xv.y * wn.y + xv.z * wn.z + xv.w * wn.w;
        }
    }
#pragma unroll
    for (int j = 0; j < NEXP; j++) {
#pragma unroll
        for (int o = 16; o > 0; o >>= 1) {
            accR[j] += __shfl_xor_sync(0xffffffffu, accR[j], o);
            accN[j] += __shfl_xor_sync(0xffffffffu, accN[j], o);
        }
    }

    if (lane == 0) {
        float noisy[NEXP];
#pragma unroll
        for (int j = 0; j < NEXP; j++) {
            const float z  = accN[j] + nb[j];
            const float sp = (z > 20.f) ? z : log1pf(expf(z));
            noisy[j] = accR[j] + rb[j] + noise[(size_t)t * NEXP + j] * sp;
        }
        int i0 = 0;
#pragma unroll
        for (int j = 1; j < NEXP; j++) if (noisy[j] > noisy[i0]) i0 = j;
        int i1 = (i0 == 0) ? 1 : 0;
#pragma unroll
        for (int j = 0; j < NEXP; j++)
            if (j != i0 && noisy[j] > noisy[i1]) i1 = j;

        const float v0 = noisy[i0], v1 = noisy[i1];
        const float g0 = 1.f / (1.f + expf(v1 - v0));
        const float g1 = 1.f / (1.f + expf(v0 - v1));

        int p0 = atomicAdd(&g_cnt[i0], 1);
        g_tok[i0 * CAP + p0]  = t;
        g_gate[i0 * CAP + p0] = g0;
        int p1 = atomicAdd(&g_cnt[i1], 1);
        g_tok[i1 * CAP + p1]  = t;
        g_gate[i1 * CAP + p1] = g1;
    }
}

__global__ void k_nop() {}

// ---------------------------------------------------------------------------
// One k-tile (64 halves) of fp16 HMMA. Warp tile 64(M) x 32(N).
// ---------------------------------------------------------------------------
__device__ __forceinline__ void compute_ktile(
    uint32_t stage, uint32_t aOff, uint32_t aSwz, uint32_t aKl,
    uint32_t bOff, uint32_t bSwz, uint32_t bKl, float acc[4][4][4])
{
#pragma unroll
    for (int ks = 0; ks < 4; ks++) {
        uint32_t af[4][4], bf[2][4];
        const uint32_t acb = ((uint32_t)(ks * 32) + aKl) ^ aSwz;
        const uint32_t bcb = ((uint32_t)(ks * 32) + bKl) ^ bSwz;
#pragma unroll
        for (int mi = 0; mi < 4; mi++)
            ldsm_x4(af[mi], stage + aOff + mi * 2048 + acb);
#pragma unroll
        for (int nj = 0; nj < 2; nj++)
            ldsm_x4(bf[nj], stage + bOff + nj * 2048 + bcb);
#pragma unroll
        for (int mi = 0; mi < 4; mi++)
#pragma unroll
            for (int ni = 0; ni < 4; ni++)
                mma_f16(acc[mi][ni], af[mi], &bf[ni >> 1][(ni & 1) * 2]);
    }
}

__device__ __forceinline__ void stage_C(
    float* sC, int warp_m, int warp_n, int lane, float acc[4][4][4])
{
    const int lr = lane >> 2;
    const int lc = (lane & 3) * 2;
#pragma unroll
    for (int mi = 0; mi < 4; mi++)
#pragma unroll
        for (int ni = 0; ni < 4; ni++) {
            float* p = sC + (warp_m + mi * 16 + lr) * SC_LD + warp_n + ni * 8 + lc;
            p[0] = acc[mi][ni][0];
            p[1] = acc[mi][ni][1];
            p[8 * SC_LD]     = acc[mi][ni][2];
            p[8 * SC_LD + 1] = acc[mi][ni][3];
        }
}

// ---------------------------------------------------------------------------
// GEMM1 (fp16): C[128x128]: cols [0,64)=X@w1^T slice, [64,128)=X@w3^T slice.
// Epilogue: gate * SwiGLU -> g_hh (fp16).
// ---------------------------------------------------------------------------
__global__ void __launch_bounds__(256, 2) k_gemm1()
{
    const int e    = blockIdx.z;
    const int cnt  = g_cnt[e];
    const int row0 = blockIdx.x * 128;
    if (row0 >= cnt) return;
    const int n0 = blockIdx.y * 64;

    extern __shared__ char dynsmem[];
    const uint32_t sbu = smem_u32(dynsmem);

    const int tid  = threadIdx.x;
    const int warp = tid >> 5;
    const int lane = tid & 31;
    const int warp_m = (warp >> 2) * 64;
    const int warp_n = (warp & 3) * 32;

    const int* tokp = g_tok + e * CAP + row0;
    const __half* aSrc[4]; const __half* bSrc[4];
    uint32_t dOff[4];
#pragma unroll
    for (int i = 0; i < 4; i++) {
        const int idx = i * 256 + tid;
        const int r = idx >> 3, seg = idx & 7;
        const int tk = (row0 + r < cnt) ? tokp[r] : 0;
        aSrc[i] = g_xh + (size_t)tk * DMODEL + seg * 8;
        bSrc[i] = (r < 64)
                ? g_w1h + ((size_t)e * HDIM + n0 + r)      * DMODEL + seg * 8
                : g_w3h + ((size_t)e * HDIM + n0 + r - 64) * DMODEL + seg * 8;
        dOff[i] = SWOFF(r, seg);
    }

    const int aR = warp_m + (lane & 15);
    const uint32_t aOff = (uint32_t)aR * 128;
    const uint32_t aSwz = (uint32_t)(aR & 7) << 4;
    const uint32_t aKl  = (uint32_t)(lane >> 4) << 4;
    const int bR = warp_n + ((lane >> 4) << 3) + (lane & 7);
    const uint32_t bOff = (uint32_t)ABUF + (uint32_t)bR * 128;
    const uint32_t bSwz = (uint32_t)(bR & 7) << 4;
    const uint32_t bKl  = ((uint32_t)(lane >> 3) & 1) << 4;

    float acc[4][4][4];
#pragma unroll
    for (int a = 0; a < 4; a++)
#pragma unroll
        for (int b = 0; b < 4; b++)
#pragma unroll
            for (int c = 0; c < 4; c++) acc[a][b][c] = 0.f;

#pragma unroll
    for (int p = 0; p < 2; p++) {
        const uint32_t sb = sbu + p * STAGE;
#pragma unroll
        for (int i = 0; i < 4; i++) {
            CP_ASYNC16(sb + dOff[i],        aSrc[i] + p * KTILE);
            CP_ASYNC16(sb + ABUF + dOff[i], bSrc[i] + p * KTILE);
        }
        CP_COMMIT();
    }

    const int NKT = DMODEL / KTILE;   // 16
    for (int it = 0; it < NKT; ++it) {
        CP_WAIT(1);
        __syncthreads();
        compute_ktile(sbu + (it % 3) * STAGE, aOff, aSwz, aKl, bOff, bSwz, bKl, acc);
        if (it + 2 < NKT) {
            const uint32_t sb = sbu + ((it + 2) % 3) * STAGE;
            const int k0 = (it + 2) * KTILE;
#pragma unroll
            for (int i = 0; i < 4; i++) {
                CP_ASYNC16(sb + dOff[i],        aSrc[i] + k0);
                CP_ASYNC16(sb + ABUF + dOff[i], bSrc[i] + k0);
            }
        }
        CP_COMMIT();
    }
    __syncthreads();

    float* sC = (float*)dynsmem;
    stage_C(sC, warp_m, warp_n, lane, acc);
    __syncthreads();

    const int r    = tid >> 1;
    const int half = tid & 1;
    const float g  = g_gate[e * CAP + row0 + r];      // gate folded into h
    const float* c1 = sC + r * SC_LD + half * 32;
    const float* c3 = c1 + 64;
    __half* hp = g_hh + ((size_t)e * CAP + row0 + r) * HDIM + n0 + half * 32;
#pragma unroll
    for (int j = 0; j < 32; j += 8) {
        float s[8];
#pragma unroll
        for (int q = 0; q < 8; q++) {
            const float v = c1[j + q];
            s[q] = g * (v / (1.f + expf(-v))) * c3[j + q];
        }
        uint4 o;
        o.x = pack2(s[0], s[1]); o.y = pack2(s[2], s[3]);
        o.z = pack2(s[4], s[5]); o.w = pack2(s[6], s[7]);
        *(uint4*)(hp + j) = o;
    }
}

// ---------------------------------------------------------------------------
// GEMM2 (fp16, split-K=2): out[tok] += (gate*h) @ w2^T, tile 128 x 128,
// K = 1024 per block. blockIdx.z = e*2 + kHalf. 4 red-adds per out element.
// ---------------------------------------------------------------------------
__global__ void __launch_bounds__(256, 2) k_gemm2(float* __restrict__ out)
{
    const int e     = blockIdx.z >> 1;
    const int kh    = blockIdx.z & 1;
    const int cnt   = g_cnt[e];
    const int row0  = blockIdx.x * 128;
    if (row0 >= cnt) return;
    const int n0 = blockIdx.y * 128;
    const int kBase = kh * (HDIM / 2);

    extern __shared__ char dynsmem[];
    const uint32_t sbu = smem_u32(dynsmem);

    const int tid  = threadIdx.x;
    const int warp = tid >> 5;
    const int lane = tid & 31;
    const int warp_m = (warp >> 2) * 64;
    const int warp_n = (warp & 3) * 32;

    const __half* aSrc[4]; const __half* bSrc[4];
    uint32_t dOff[4];
#pragma unroll
    for (int i = 0; i < 4; i++) {
        const int idx = i * 256 + tid;
        const int r = idx >> 3, seg = idx & 7;
        aSrc[i] = g_hh  + ((size_t)e * CAP + row0 + r) * HDIM + kBase + seg * 8;
        bSrc[i] = g_w2h + ((size_t)e * DMODEL + n0 + r) * HDIM + kBase + seg * 8;
        dOff[i] = SWOFF(r, seg);
    }

    const int aR = warp_m + (lane & 15);
    const uint32_t aOff = (uint32_t)aR * 128;
    const uint32_t aSwz = (uint32_t)(aR & 7) << 4;
    const uint32_t aKl  = (uint32_t)(lane >> 4) << 4;
    const int bR = warp_n + ((lane >> 4) << 3) + (lane & 7);
    const uint32_t bOff = (uint32_t)ABUF + (uint32_t)bR * 128;
    const uint32_t bSwz = (uint32_t)(bR & 7) << 4;
    const uint32_t bKl  = ((uint32_t)(lane >> 3) & 1) << 4;

    float acc[4][4][4];
#pragma unroll
    for (int a = 0; a < 4; a++)
#pragma unroll
        for (int b = 0; b < 4; b++)
#pragma unroll
            for (int c = 0; c < 4; c++) acc[a][b][c] = 0.f;

#pragma unroll
    for (int p = 0; p < 2; p++) {
        const uint32_t sb = sbu + p * STAGE;
#pragma unroll
        for (int i = 0; i < 4; i++) {
            CP_ASYNC16(sb + dOff[i],        aSrc[i] + p * KTILE);
            CP_ASYNC16(sb + ABUF + dOff[i], bSrc[i] + p * KTILE);
        }
        CP_COMMIT();
    }

    const int NKT = (HDIM / 2) / KTILE;   // 16
    for (int it = 0; it < NKT; ++it) {
        CP_WAIT(1);
        __syncthreads();
        compute_ktile(sbu + (it % 3) * STAGE, aOff, aSwz, aKl, bOff, bSwz, bKl, acc);
        if (it + 2 < NKT) {
            const uint32_t sb = sbu + ((it + 2) % 3) * STAGE;
            const int k0 = (it + 2) * KTILE;
#pragma unroll
            for (int i = 0; i < 4; i++) {
                CP_ASYNC16(sb + dOff[i],        aSrc[i] + k0);
                CP_ASYNC16(sb + ABUF + dOff[i], bSrc[i] + k0);
            }
        }
        CP_COMMIT();
    }
    __syncthreads();

    float* sC = (float*)dynsmem;
    stage_C(sC, warp_m, warp_n, lane, acc);
    __syncthreads();

    const int r    = tid >> 1;
    const int half = tid & 1;
    const int m = row0 + r;
    if (m < cnt) {
        const int t = g_tok[e * CAP + m];
        float* op = out + (size_t)t * DMODEL + n0 + half * 64;
        const float* cp = sC + r * SC_LD + half * 64;
#pragma unroll
        for (int j = 0; j < 64; j += 4)
            red_add_v4(op + j, cp[j], cp[j + 1], cp[j + 2], cp[j + 3]);
    }
}

// ---------------------------------------------------------------------------
extern "C" void kernel_launch(void* const* d_in, const int* in_sizes, int n_in,
                              void* d_out, int out_size)
{
    const float* x     = (const float*)d_in[0];
    const float* noise = (const float*)d_in[1];
    const float* rw    = (const float*)d_in[2];
    const float* rb    = (const float*)d_in[3];
    const float* nw    = (const float*)d_in[4];
    const float* nb    = (const float*)d_in[5];
    const float* w1    = (const float*)d_in[6];
    const float* w2    = (const float*)d_in[7];
    const float* w3    = (const float*)d_in[8];
    float* out = (float*)d_out;

    cudaFuncSetAttribute(k_gemm1, cudaFuncAttributeMaxDynamicSharedMemorySize, SMEM_BYTES);
    cudaFuncSetAttribute(k_gemm2, cudaFuncAttributeMaxDynamicSharedMemorySize, SMEM_BYTES);

    void* cntp = nullptr;
    cudaGetSymbolAddress(&cntp, g_cnt);
    cudaMemsetAsync(cntp, 0, NEXP * sizeof(int));

    const int nBlocks = RB + ZB + 3 * CB;                             // 33792
    k_prep<<<nBlocks, 256>>>(x, noise, rw, rb, nw, nb,                // kernel 0
                             (const float4*)w1, (const float4*)w3,
                             (const float4*)w2, (float4*)out);

    k_nop<<<1, 1>>>();                                                // kernel 1
    k_nop<<<1, 1>>>();                                                // kernel 2

    dim3 g1(CAP / 128, HDIM / 64, NEXP);
    k_gemm1<<<g1, 256, SMEM_BYTES>>>();                               // kernel 3 (ncu)

    dim3 g2(CAP / 128, DMODEL / 128, NEXP * 2);
    k_gemm2<<<g2, 256, SMEM_BYTES>>>(out);                            // kernel 4
}

// round 9
// speedup vs baseline: 1.0729x; 1.0729x over previous
#include <cuda_runtime.h>
#include <cuda_fp16.h>
#include <math.h>
#include <stdint.h>

#define T_TOK  8192
#define DMODEL 1024
#define HDIM   2048
#define NEXP   8
#define CAP    8192

#define KTILE  64                         // k-tile in halves (128 B rows)
#define ABUF   (128 * 128)                // 16384 B per 128 x 64-half tile
#define STAGE  (2 * ABUF)                 // A + B per stage
#define SMEM_BYTES (3 * STAGE)            // 98304 B, 3-stage pipeline
#define SC_LD  132                        // fp32 C staging stride (gemm2)

// prep kernel block regions
#define RB    1024                        // router blocks (8 warps each)
#define ZB    8192                        // out-zero blocks
#define CB    8192                        // cvt blocks per weight

// ---------------- device scratch (static, allocation-free) ----------------
__device__ int    g_cnt[NEXP];
__device__ int    g_tok[NEXP * CAP];
__device__ float  g_gate[NEXP * CAP];
__device__ __half g_xh[(size_t)T_TOK * DMODEL];
__device__ __half g_w1h[(size_t)NEXP * HDIM * DMODEL];
__device__ __half g_w3h[(size_t)NEXP * HDIM * DMODEL];
__device__ __half g_w2h[(size_t)NEXP * DMODEL * HDIM];
__device__ __half g_hh[(size_t)NEXP * CAP * HDIM];

// ---------------- PTX helpers (plain sm_80/sm_90-class) ----------------
__device__ __forceinline__ uint32_t smem_u32(const void* p) {
    uint32_t a;
    asm("{ .reg .u64 t; cvta.to.shared.u64 t, %1; cvt.u32.u64 %0, t; }" : "=r"(a) : "l"(p));
    return a;
}
#define CP_ASYNC16(dst, src) \
    asm volatile("cp.async.cg.shared.global [%0], [%1], 16;" :: "r"(dst), "l"(src))
#define CP_COMMIT() asm volatile("cp.async.commit_group;" ::: "memory")
#define CP_WAIT(n)  asm volatile("cp.async.wait_group %0;" :: "n"(n) : "memory")

__device__ __forceinline__ void ldsm_x4(uint32_t* r, uint32_t addr) {
    asm volatile("ldmatrix.sync.aligned.m8n8.x4.shared.b16 {%0,%1,%2,%3}, [%4];"
                 : "=r"(r[0]), "=r"(r[1]), "=r"(r[2]), "=r"(r[3]) : "r"(addr));
}
__device__ __forceinline__ void mma_f16(float* c, const uint32_t* a, const uint32_t* b) {
    asm volatile("mma.sync.aligned.m16n8k16.row.col.f32.f16.f16.f32 "
                 "{%0,%1,%2,%3}, {%4,%5,%6,%7}, {%8,%9}, {%0,%1,%2,%3};"
                 : "+f"(c[0]), "+f"(c[1]), "+f"(c[2]), "+f"(c[3])
                 : "r"(a[0]), "r"(a[1]), "r"(a[2]), "r"(a[3]), "r"(b[0]), "r"(b[1]));
}
__device__ __forceinline__ uint32_t pack2(float lo, float hi) {
    __half2 h = __floats2half2_rn(lo, hi);
    return *reinterpret_cast<uint32_t*>(&h);
}
__device__ __forceinline__ void red_add_v4(float* p, float a, float b, float c, float d) {
    asm volatile("red.global.add.v4.f32 [%0], {%1, %2, %3, %4};"
                 :: "l"(p), "f"(a), "f"(b), "f"(c), "f"(d) : "memory");
}

// swizzled smem byte offset for row r (128B rows), 16B segment s (0..7)
#define SWOFF(r, s16) ((uint32_t)((r) * 128 + (((s16) * 16) ^ (((r) & 7) << 4))))

// ---------------------------------------------------------------------------
// k_prep: fused router + out-zero + 3x weight fp32->fp16 convert.
// ---------------------------------------------------------------------------
__global__ void __launch_bounds__(256) k_prep(
    const float* __restrict__ x, const float* __restrict__ noise,
    const float* __restrict__ rw, const float* __restrict__ rb,
    const float* __restrict__ nw, const float* __restrict__ nb,
    const float4* __restrict__ w1, const float4* __restrict__ w3,
    const float4* __restrict__ w2, float4* __restrict__ out)
{
    const int b   = blockIdx.x;
    const int tid = threadIdx.x;

    if (b >= RB) {
        const int rb_ = b - RB;
        if (rb_ < ZB) {                                   // zero out (float4)
            out[(size_t)rb_ * 256 + tid] = make_float4(0.f, 0.f, 0.f, 0.f);
        } else {                                          // weight convert
            const int region = (rb_ - ZB) / CB;
            const size_t i = (size_t)((rb_ - ZB) % CB) * 256 + tid;
            const float4* s = (region == 0) ? w1 : (region == 1) ? w3 : w2;
            uint4* d = (uint4*)((region == 0) ? g_w1h : (region == 1) ? g_w3h : g_w2h);
            const float4 a0 = s[2 * i], b0 = s[2 * i + 1];
            uint4 o;
            o.x = pack2(a0.x, a0.y); o.y = pack2(a0.z, a0.w);
            o.z = pack2(b0.x, b0.y); o.w = pack2(b0.z, b0.w);
            d[i] = o;
        }
        return;
    }

    // ---- router: 8 warps, one token per warp ----
    const int warp = tid >> 5;
    const int lane = tid & 31;
    const int t = b * 8 + warp;

    const float4* xp  = (const float4*)(x + (size_t)t * DMODEL);
    const float4* rw4 = (const float4*)rw;
    const float4* nw4 = (const float4*)nw;
    uint2* xh = (uint2*)(g_xh + (size_t)t * DMODEL);

    float accR[NEXP], accN[NEXP];
#pragma unroll
    for (int j = 0; j < NEXP; j++) { accR[j] = 0.f; accN[j] = 0.f; }

#pragma unroll
    for (int it = 0; it < 8; it++) {
        const int d4 = it * 32 + lane;
        const float4 xv = xp[d4];
        uint2 p; p.x = pack2(xv.x, xv.y); p.y = pack2(xv.z, xv.w);
        xh[d4] = p;
#pragma unroll
        for (int j = 0; j < NEXP; j++) {
            const float4 w  = __ldg(rw4 + j * 256 + d4);
            accR[j] += xv.x * w.x + xv.y * w.y + xv.z * w.z + xv.w * w.w;
            const float4 wn = __ldg(nw4 + j * 256 + d4);
            accN[j] += xv.x * wn.x + xv.y * wn.y + xv.z * wn.z + xv.w * wn.w;
        }
    }
#pragma unroll
    for (int j = 0; j < NEXP; j++) {
#pragma unroll
        for (int o = 16; o > 0; o >>= 1) {
            accR[j] += __shfl_xor_sync(0xffffffffu, accR[j], o);
            accN[j] += __shfl_xor_sync(0xffffffffu, accN[j], o);
        }
    }

    if (lane == 0) {
        float noisy[NEXP];
#pragma unroll
        for (int j = 0; j < NEXP; j++) {
            const float z  = accN[j] + nb[j];
            const float sp = (z > 20.f) ? z : log1pf(expf(z));
            noisy[j] = accR[j] + rb[j] + noise[(size_t)t * NEXP + j] * sp;
        }
        int i0 = 0;
#pragma unroll
        for (int j = 1; j < NEXP; j++) if (noisy[j] > noisy[i0]) i0 = j;
        int i1 = (i0 == 0) ? 1 : 0;
#pragma unroll
        for (int j = 0; j < NEXP; j++)
            if (j != i0 && noisy[j] > noisy[i1]) i1 = j;

        const float v0 = noisy[i0], v1 = noisy[i1];
        const float g0 = 1.f / (1.f + expf(v1 - v0));
        const float g1 = 1.f / (1.f + expf(v0 - v1));

        int p0 = atomicAdd(&g_cnt[i0], 1);
        g_tok[i0 * CAP + p0]  = t;
        g_gate[i0 * CAP + p0] = g0;
        int p1 = atomicAdd(&g_cnt[i1], 1);
        g_tok[i1 * CAP + p1]  = t;
        g_gate[i1 * CAP + p1] = g1;
    }
}

__global__ void k_nop() {}

// ---------------------------------------------------------------------------
// One k-tile (64 halves) of fp16 HMMA. Warp tile 64(M) x 32(N).
// ---------------------------------------------------------------------------
__device__ __forceinline__ void compute_ktile(
    uint32_t stage, uint32_t aOff, uint32_t aSwz, uint32_t aKl,
    uint32_t bOff, uint32_t bSwz, uint32_t bKl, float acc[4][4][4])
{
#pragma unroll
    for (int ks = 0; ks < 4; ks++) {
        uint32_t af[4][4], bf[2][4];
        const uint32_t acb = ((uint32_t)(ks * 32) + aKl) ^ aSwz;
        const uint32_t bcb = ((uint32_t)(ks * 32) + bKl) ^ bSwz;
#pragma unroll
        for (int mi = 0; mi < 4; mi++)
            ldsm_x4(af[mi], stage + aOff + mi * 2048 + acb);
#pragma unroll
        for (int nj = 0; nj < 2; nj++)
            ldsm_x4(bf[nj], stage + bOff + nj * 2048 + bcb);
#pragma unroll
        for (int mi = 0; mi < 4; mi++)
#pragma unroll
            for (int ni = 0; ni < 4; ni++)
                mma_f16(acc[mi][ni], af[mi], &bf[ni >> 1][(ni & 1) * 2]);
    }
}

__device__ __forceinline__ void stage_C(
    float* sC, int warp_m, int warp_n, int lane, float acc[4][4][4])
{
    const int lr = lane >> 2;
    const int lc = (lane & 3) * 2;
#pragma unroll
    for (int mi = 0; mi < 4; mi++)
#pragma unroll
        for (int ni = 0; ni < 4; ni++) {
            float* p = sC + (warp_m + mi * 16 + lr) * SC_LD + warp_n + ni * 8 + lc;
            p[0] = acc[mi][ni][0];
            p[1] = acc[mi][ni][1];
            p[8 * SC_LD]     = acc[mi][ni][2];
            p[8 * SC_LD + 1] = acc[mi][ni][3];
        }
}

// ---------------------------------------------------------------------------
// GEMM1 (fp16): per warp, ni 0-1 = w1 cols [c..c+16), ni 2-3 = SAME w3 cols.
// SwiGLU computed directly from acc registers; gate folded; h -> g_hh (fp16).
// B smem row r: g=r>>3, q=r&7, warp w'=g>>2, gi=g&3:
//   gi<2 -> w1 col n0+16w'+gi*8+q ; gi>=2 -> w3 col n0+16w'+(gi-2)*8+q
// ---------------------------------------------------------------------------
__global__ void __launch_bounds__(256, 2) k_gemm1()
{
    const int e    = blockIdx.z;
    const int cnt  = g_cnt[e];
    const int row0 = blockIdx.x * 128;
    if (row0 >= cnt) return;
    const int n0 = blockIdx.y * 64;

    extern __shared__ char dynsmem[];
    const uint32_t sbu = smem_u32(dynsmem);

    const int tid  = threadIdx.x;
    const int warp = tid >> 5;
    const int lane = tid & 31;
    const int warp_m = (warp >> 2) * 64;
    const int warp_n = (warp & 3) * 32;

    const int* tokp = g_tok + e * CAP + row0;
    const __half* aSrc[4]; const __half* bSrc[4];
    uint32_t dOff[4];
#pragma unroll
    for (int i = 0; i < 4; i++) {
        const int idx = i * 256 + tid;
        const int r = idx >> 3, seg = idx & 7;
        const int tk = (row0 + r < cnt) ? tokp[r] : 0;
        aSrc[i] = g_xh + (size_t)tk * DMODEL + seg * 8;
        // interleaved w1/w3 column mapping
        const int gq = r >> 3, q = r & 7;
        const int wp = gq >> 2, gi = gq & 3;
        const int colRow = n0 + wp * 16 + (gi & 1) * 8 + q;
        bSrc[i] = ((gi < 2) ? g_w1h : g_w3h)
                + ((size_t)e * HDIM + colRow) * DMODEL + seg * 8;
        dOff[i] = SWOFF(r, seg);
    }

    const int aR = warp_m + (lane & 15);
    const uint32_t aOff = (uint32_t)aR * 128;
    const uint32_t aSwz = (uint32_t)(aR & 7) << 4;
    const uint32_t aKl  = (uint32_t)(lane >> 4) << 4;
    const int bR = warp_n + ((lane >> 4) << 3) + (lane & 7);
    const uint32_t bOff = (uint32_t)ABUF + (uint32_t)bR * 128;
    const uint32_t bSwz = (uint32_t)(bR & 7) << 4;
    const uint32_t bKl  = ((uint32_t)(lane >> 3) & 1) << 4;

    float acc[4][4][4];
#pragma unroll
    for (int a = 0; a < 4; a++)
#pragma unroll
        for (int b = 0; b < 4; b++)
#pragma unroll
            for (int c = 0; c < 4; c++) acc[a][b][c] = 0.f;

#pragma unroll
    for (int p = 0; p < 2; p++) {
        const uint32_t sb = sbu + p * STAGE;
#pragma unroll
        for (int i = 0; i < 4; i++) {
            CP_ASYNC16(sb + dOff[i],        aSrc[i] + p * KTILE);
            CP_ASYNC16(sb + ABUF + dOff[i], bSrc[i] + p * KTILE);
        }
        CP_COMMIT();
    }

    const int NKT = DMODEL / KTILE;   // 16
    for (int it = 0; it < NKT; ++it) {
        CP_WAIT(1);
        __syncthreads();
        compute_ktile(sbu + (it % 3) * STAGE, aOff, aSwz, aKl, bOff, bSwz, bKl, acc);
        if (it + 2 < NKT) {
            const uint32_t sb = sbu + ((it + 2) % 3) * STAGE;
            const int k0 = (it + 2) * KTILE;
#pragma unroll
            for (int i = 0; i < 4; i++) {
                CP_ASYNC16(sb + dOff[i],        aSrc[i] + k0);
                CP_ASYNC16(sb + ABUF + dOff[i], bSrc[i] + k0);
            }
        }
        CP_COMMIT();
    }

    // direct-register SwiGLU epilogue (no SMEM staging, no extra syncs)
    const int lr = lane >> 2;
    const int lc = (lane & 3) * 2;
    const int colBase = n0 + (warp & 3) * 16 + lc;
#pragma unroll
    for (int mi = 0; mi < 4; mi++) {
        const int rA = row0 + warp_m + mi * 16 + lr;        // rows lr and lr+8
        const float gA = g_gate[e * CAP + rA];
        const float gB = g_gate[e * CAP + rA + 8];
        __half* hA = g_hh + ((size_t)e * CAP + rA) * HDIM;
        __half* hB = hA + (size_t)8 * HDIM;
#pragma unroll
        for (int ni = 0; ni < 2; ni++) {
            const float* c1 = acc[mi][ni];
            const float* c3 = acc[mi][ni + 2];
            float v, s0, s1;
            v = c1[0]; s0 = gA * (v / (1.f + expf(-v))) * c3[0];
            v = c1[1]; s1 = gA * (v / (1.f + expf(-v))) * c3[1];
            *(uint32_t*)(hA + colBase + ni * 8) = pack2(s0, s1);
            v = c1[2]; s0 = gB * (v / (1.f + expf(-v))) * c3[2];
            v = c1[3]; s1 = gB * (v / (1.f + expf(-v))) * c3[3];
            *(uint32_t*)(hB + colBase + ni * 8) = pack2(s0, s1);
        }
    }
}

// ---------------------------------------------------------------------------
// GEMM2 (fp16): out[tok] += (gate*h) @ w2^T, tile 128 x 128, K = 2048.
// h already carries the gate. 2 red-adds per out element.
// ---------------------------------------------------------------------------
__global__ void __launch_bounds__(256, 2) k_gemm2(float* __restrict__ out)
{
    const int e    = blockIdx.z;
    const int cnt  = g_cnt[e];
    const int row0 = blockIdx.x * 128;
    if (row0 >= cnt) return;
    const int n0 = blockIdx.y * 128;

    extern __shared__ char dynsmem[];
    const uint32_t sbu = smem_u32(dynsmem);

    const int tid  = threadIdx.x;
    const int warp = tid >> 5;
    const int lane = tid & 31;
    const int warp_m = (warp >> 2) * 64;
    const int warp_n = (warp & 3) * 32;

    const __half* aSrc[4]; const __half* bSrc[4];
    uint32_t dOff[4];
#pragma unroll
    for (int i = 0; i < 4; i++) {
        const int idx = i * 256 + tid;
        const int r = idx >> 3, seg = idx & 7;
        aSrc[i] = g_hh  + ((size_t)e * CAP + row0 + r) * HDIM + seg * 8;
        bSrc[i] = g_w2h + ((size_t)e * DMODEL + n0 + r) * HDIM + seg * 8;
        dOff[i] = SWOFF(r, seg);
    }

    const int aR = warp_m + (lane & 15);
    const uint32_t aOff = (uint32_t)aR * 128;
    const uint32_t aSwz = (uint32_t)(aR & 7) << 4;
    const uint32_t aKl  = (uint32_t)(lane >> 4) << 4;
    const int bR = warp_n + ((lane >> 4) << 3) + (lane & 7);
    const uint32_t bOff = (uint32_t)ABUF + (uint32_t)bR * 128;
    const uint32_t bSwz = (uint32_t)(bR & 7) << 4;
    const uint32_t bKl  = ((uint32_t)(lane >> 3) & 1) << 4;

    float acc[4][4][4];
#pragma unroll
    for (int a = 0; a < 4; a++)
#pragma unroll
        for (int b = 0; b < 4; b++)
#pragma unroll
            for (int c = 0; c < 4; c++) acc[a][b][c] = 0.f;

#pragma unroll
    for (int p = 0; p < 2; p++) {
        const uint32_t sb = sbu + p * STAGE;
#pragma unroll
        for (int i = 0; i < 4; i++) {
            CP_ASYNC16(sb + dOff[i],        aSrc[i] + p * KTILE);
            CP_ASYNC16(sb + ABUF + dOff[i], bSrc[i] + p * KTILE);
        }
        CP_COMMIT();
    }

    const int NKT = HDIM / KTILE;   // 32
    for (int it = 0; it < NKT; ++it) {
        CP_WAIT(1);
        __syncthreads();
        compute_ktile(sbu + (it % 3) * STAGE, aOff, aSwz, aKl, bOff, bSwz, bKl, acc);
        if (it + 2 < NKT) {
            const uint32_t sb = sbu + ((it + 2) % 3) * STAGE;
            const int k0 = (it + 2) * KTILE;
#pragma unroll
            for (int i = 0; i < 4; i++) {
                CP_ASYNC16(sb + dOff[i],        aSrc[i] + k0);
                CP_ASYNC16(sb + ABUF + dOff[i], bSrc[i] + k0);
            }
        }
        CP_COMMIT();
    }
    __syncthreads();

    float* sC = (float*)dynsmem;
    stage_C(sC, warp_m, warp_n, lane, acc);
    __syncthreads();

    const int r    = tid >> 1;
    const int half = tid & 1;
    const int m = row0 + r;
    if (m < cnt) {
        const int t = g_tok[e * CAP + m];
        float* op = out + (size_t)t * DMODEL + n0 + half * 64;
        const float* cp = sC + r * SC_LD + half * 64;
#pragma unroll
        for (int j = 0; j < 64; j += 4)
            red_add_v4(op + j, cp[j], cp[j + 1], cp[j + 2], cp[j + 3]);
    }
}

// ---------------------------------------------------------------------------
extern "C" void kernel_launch(void* const* d_in, const int* in_sizes, int n_in,
                              void* d_out, int out_size)
{
    const float* x     = (const float*)d_in[0];
    const float* noise = (const float*)d_in[1];
    const float* rw    = (const float*)d_in[2];
    const float* rb    = (const float*)d_in[3];
    const float* nw    = (const float*)d_in[4];
    const float* nb    = (const float*)d_in[5];
    const float* w1    = (const float*)d_in[6];
    const float* w2    = (const float*)d_in[7];
    const float* w3    = (const float*)d_in[8];
    float* out = (float*)d_out;

    cudaFuncSetAttribute(k_gemm1, cudaFuncAttributeMaxDynamicSharedMemorySize, SMEM_BYTES);
    cudaFuncSetAttribute(k_gemm2, cudaFuncAttributeMaxDynamicSharedMemorySize, SMEM_BYTES);

    void* cntp = nullptr;
    cudaGetSymbolAddress(&cntp, g_cnt);
    cudaMemsetAsync(cntp, 0, NEXP * sizeof(int));

    const int nBlocks = RB + ZB + 3 * CB;                             // 33792
    k_prep<<<nBlocks, 256>>>(x, noise, rw, rb, nw, nb,                // kernel 0
                             (const float4*)w1, (const float4*)w3,
                             (const float4*)w2, (float4*)out);

    dim3 g1(CAP / 128, HDIM / 64, NEXP);
    k_gemm1<<<g1, 256, SMEM_BYTES>>>();                               // kernel 1

    k_nop<<<1, 1>>>();                                                // kernel 2

    dim3 g2(CAP / 128, DMODEL / 128, NEXP);
    k_gemm2<<<g2, 256, SMEM_BYTES>>>(out);                            // kernel 3 (ncu)
}